// round 14
// baseline (speedup 1.0000x reference)
#include <cuda_runtime.h>
#include <cuda_bf16.h>
#include <math.h>
#include <stdint.h>

#define BB 32
#define SS 1024
#define CC 384
#define HH 384
#define MAX_OUT_T 3072
#define M_TOTAL (BB*SS)          // 32768
#define M_HALF  (M_TOTAL/2)      // 16384 (multiple of SS -> halo-safe split)
#define KDIM (3*CC)              // 1152
#define PRED_OFFSET ((size_t)BB*MAX_OUT_T*CC)

// ---------------- scratch (static device globals: allocation-free) ----------
__device__ __nv_bfloat16 g_wt1 [(size_t)HH*KDIM];
__device__ __nv_bfloat16 g_wt2 [(size_t)HH*KDIM];
__device__ __nv_bfloat16 g_t1b [(size_t)M_TOTAL*HH];   // GEMM1 out (bf16, pre-LN)
__device__ __nv_bfloat16 g_t2b [(size_t)M_TOTAL*HH];   // GEMM2 out (bf16, pre-LN)
__device__ float2 g_stats[M_TOTAL];                     // per-row {mu, rs} of t1b
__device__ int   g_cum[BB*SS];

// ---------------- PTX helpers (baseline PTX only) ----------------------------
__device__ __forceinline__ uint32_t smem_u32(const void* p) {
    uint32_t a;
    asm("{ .reg .u64 t; cvta.to.shared.u64 t, %1; cvt.u32.u64 %0, t; }" : "=r"(a) : "l"(p));
    return a;
}
__device__ __forceinline__ void cp_async16(uint32_t saddr, const void* gptr, uint32_t sz) {
    asm volatile("cp.async.cg.shared.global [%0], [%1], 16, %2;"
                 :: "r"(saddr), "l"(gptr), "r"(sz) : "memory");
}
__device__ __forceinline__ void cp_commit() {
    asm volatile("cp.async.commit_group;" ::: "memory");
}
template <int N>
__device__ __forceinline__ void cp_wait() {
    asm volatile("cp.async.wait_group %0;" :: "n"(N) : "memory");
}
__device__ __forceinline__ void ldmatrix_x4(uint32_t& r0, uint32_t& r1, uint32_t& r2,
                                            uint32_t& r3, uint32_t addr) {
    asm volatile("ldmatrix.sync.aligned.m8n8.x4.shared.b16 {%0,%1,%2,%3}, [%4];"
                 : "=r"(r0), "=r"(r1), "=r"(r2), "=r"(r3) : "r"(addr));
}
__device__ __forceinline__ void mma_16816(float& d0, float& d1, float& d2, float& d3,
                                          uint32_t a0, uint32_t a1, uint32_t a2, uint32_t a3,
                                          uint32_t b0, uint32_t b1) {
    asm volatile("mma.sync.aligned.m16n8k16.row.col.f32.bf16.bf16.f32 "
                 "{%0,%1,%2,%3}, {%4,%5,%6,%7}, {%8,%9}, {%0,%1,%2,%3};"
                 : "+f"(d0), "+f"(d1), "+f"(d2), "+f"(d3)
                 : "r"(a0), "r"(a1), "r"(a2), "r"(a3), "r"(b0), "r"(b1));
}

// ---------------------------------------------------------------------------
// Conv-as-GEMM (round-12 structure: 3-tap A reuse, B 4-slot cp.async ring).
// A path is now produced in-kernel:
//   MODE 0: A = bf16(x fp32)                       (replaces f32_to_bf16)
//   MODE 1: A = relu(LN(t1b; stats, gamma, beta))  (replaces ln_relu_bf16)
// A tiles written via LDG->transform->STS; B unchanged (cp.async, wait<2>).
// ---------------------------------------------------------------------------
#define NSTEPS 18
#define A_STRIDE 17408                    // 130 rows x 128 B, padded
#define B_BASE   (2*A_STRIDE)             // 34816
#define TILE_B   16384
#define GEMM_SMEM (B_BASE + 4*TILE_B)     // 100352 -> 2 CTAs/SM

template <int MODE>
__global__ __launch_bounds__(256, 2)
void conv_gemm_fused(const void* __restrict__ Asrc,
                     const float2* __restrict__ stats,     // MODE 1
                     const float* __restrict__ gamma,      // MODE 1
                     const float* __restrict__ betap,      // MODE 1
                     const __nv_bfloat16* __restrict__ Wt,
                     const float* __restrict__ bias,
                     __nv_bfloat16* __restrict__ out)
{
    extern __shared__ __align__(1024) char smem[];
    const uint32_t sbase = smem_u32(smem);
    const int tid  = threadIdx.x;
    const int wid  = tid >> 5;
    const int lane = tid & 31;
    const int warp_m = wid & 1;
    const int warp_n = wid >> 1;
    const int n0 = blockIdx.x * 128;
    const int m0 = blockIdx.y * 128;

    const int lrow = tid >> 3;              // 0..31
    const int lcx  = (tid & 7) * 16;        // byte offset in 128B row
    const int chb  = lcx >> 1;              // channel offset of this 8-elem segment

    // A region producer: chunk j -> rows [m0-1, m0+128], channels [64j,64j+64)
    auto load_A = [&](int j) {
        char* aw = smem + (j & 1) * A_STRIDE;
        const int ch   = j * 64 + chb;
        const int seq0 = m0 & ~(SS - 1);
#pragma unroll
        for (int i = 0; i < 5; i++) {
            const int rr = lrow + 32 * i;            // 0..159
            if (rr < 130) {
                const int xr = m0 - 1 + rr;
                const bool valid = (xr >= seq0) && (xr < seq0 + SS);
                uint32_t off = (uint32_t)(rr * 128 + lcx);
                uint32_t sw  = off ^ ((off >> 3) & 0x70);
                uint4 stv = make_uint4(0u, 0u, 0u, 0u);
                if (valid) {
                    if (MODE == 0) {
                        const float4* xp = (const float4*)((const float*)Asrc
                                             + (size_t)xr * CC + ch);
                        const float4 v0 = xp[0], v1 = xp[1];
                        __nv_bfloat162 p0 = __floats2bfloat162_rn(v0.x, v0.y);
                        __nv_bfloat162 p1 = __floats2bfloat162_rn(v0.z, v0.w);
                        __nv_bfloat162 p2 = __floats2bfloat162_rn(v1.x, v1.y);
                        __nv_bfloat162 p3 = __floats2bfloat162_rn(v1.z, v1.w);
                        stv.x = *(uint32_t*)&p0; stv.y = *(uint32_t*)&p1;
                        stv.z = *(uint32_t*)&p2; stv.w = *(uint32_t*)&p3;
                    } else {
                        const uint4 raw = *(const uint4*)((const __nv_bfloat16*)Asrc
                                            + (size_t)xr * HH + ch);
                        const float2 st = stats[xr];
                        const float mu = st.x, rs = st.y;
                        const float2 f0 = __bfloat1622float2(*(const __nv_bfloat162*)&raw.x);
                        const float2 f1 = __bfloat1622float2(*(const __nv_bfloat162*)&raw.y);
                        const float2 f2 = __bfloat1622float2(*(const __nv_bfloat162*)&raw.z);
                        const float2 f3 = __bfloat1622float2(*(const __nv_bfloat162*)&raw.w);
                        const float4 gv0 = *(const float4*)(gamma + ch);
                        const float4 gv1 = *(const float4*)(gamma + ch + 4);
                        const float4 bv0 = *(const float4*)(betap + ch);
                        const float4 bv1 = *(const float4*)(betap + ch + 4);
                        float o0 = fmaxf(0.f, (f0.x - mu) * rs * gv0.x + bv0.x);
                        float o1 = fmaxf(0.f, (f0.y - mu) * rs * gv0.y + bv0.y);
                        float o2 = fmaxf(0.f, (f1.x - mu) * rs * gv0.z + bv0.z);
                        float o3 = fmaxf(0.f, (f1.y - mu) * rs * gv0.w + bv0.w);
                        float o4 = fmaxf(0.f, (f2.x - mu) * rs * gv1.x + bv1.x);
                        float o5 = fmaxf(0.f, (f2.y - mu) * rs * gv1.y + bv1.y);
                        float o6 = fmaxf(0.f, (f3.x - mu) * rs * gv1.z + bv1.z);
                        float o7 = fmaxf(0.f, (f3.y - mu) * rs * gv1.w + bv1.w);
                        __nv_bfloat162 p0 = __floats2bfloat162_rn(o0, o1);
                        __nv_bfloat162 p1 = __floats2bfloat162_rn(o2, o3);
                        __nv_bfloat162 p2 = __floats2bfloat162_rn(o4, o5);
                        __nv_bfloat162 p3 = __floats2bfloat162_rn(o6, o7);
                        stv.x = *(uint32_t*)&p0; stv.y = *(uint32_t*)&p1;
                        stv.z = *(uint32_t*)&p2; stv.w = *(uint32_t*)&p3;
                    }
                }
                *(uint4*)(aw + sw) = stv;
            }
        }
    };
    // B tile loader: b = 3j+k -> Wt rows [n0, n0+128), kc0 = k*CC + 64j
    auto load_B = [&](int b) {
        const int j = b / 3, k = b - 3 * j;
        const int kc0 = k * CC + j * 64;
        const uint32_t bbase_w = sbase + B_BASE + (uint32_t)((b & 3) * TILE_B);
#pragma unroll
        for (int i = 0; i < 4; i++) {
            const int row = lrow + 32 * i;
            uint32_t off = (uint32_t)(row * 128 + lcx);
            uint32_t sw  = off ^ ((off >> 3) & 0x70);
            const char* gp = (const char*)Wt + ((size_t)(n0 + row) * KDIM + kc0) * 2 + lcx;
            cp_async16(bbase_w + sw, gp, 16u);
        }
    };

    float acc[4][4][4];
#pragma unroll
    for (int i = 0; i < 4; i++)
#pragma unroll
        for (int j = 0; j < 4; j++)
#pragma unroll
            for (int q = 0; q < 4; q++) acc[i][j][q] = 0.f;

    const int fr_row = ((lane >> 3) & 1) * 8 + (lane & 7);
    const int fr_kb  = (lane >> 4) * 16;
    const uint32_t cxor = (uint32_t)((fr_row & 7) << 4);                 // B swizzle
    const uint32_t a_row_base = (uint32_t)((warp_m * 64 + fr_row) * 128);
    const uint32_t b_row_base = (uint32_t)((warp_n * 32 + fr_row) * 128);

    // prologue: B groups async first, then the (blocking) A producer
    load_B(0); cp_commit();
    load_B(1); cp_commit();
    load_B(2); cp_commit();
    load_A(0);

    for (int s = 0; s < NSTEPS; ++s) {
        const int j = s / 3;
        const int k = s - 3 * j;

        cp_wait<2>();
        __syncthreads();

        if (s <= NSTEPS - 4) load_B(s + 3);
        cp_commit();                        // one group per step (may be empty)
        if (k == 0 && j < 5) load_A(j + 1); // after B issue: LDG stall won't delay cp.async

        const uint32_t sa = sbase + (uint32_t)((j & 1) * A_STRIDE) + (uint32_t)(k * 128);
        const uint32_t sb = sbase + B_BASE + (uint32_t)((s & 3) * TILE_B);
        const uint32_t cxork = (uint32_t)(((fr_row + k) & 7) << 4);      // A swizzle (+k rows)

        uint32_t ball[4][2][4];
#pragma unroll
        for (int ks = 0; ks < 4; ks++) {
            const uint32_t col = ((uint32_t)(ks * 32 + fr_kb)) ^ cxor;
#pragma unroll
            for (int nt = 0; nt < 2; nt++) {
                const uint32_t addr = sb + b_row_base + (uint32_t)(nt * 2048) + col;
                ldmatrix_x4(ball[ks][nt][0], ball[ks][nt][1], ball[ks][nt][2], ball[ks][nt][3], addr);
            }
        }

#pragma unroll
        for (int ks = 0; ks < 4; ks++) {
            const uint32_t col = ((uint32_t)(ks * 32 + fr_kb)) ^ cxork;
            uint32_t a[4][4];
#pragma unroll
            for (int mt = 0; mt < 4; mt++) {
                const uint32_t addr = sa + a_row_base + (uint32_t)(mt * 2048) + col;
                ldmatrix_x4(a[mt][0], a[mt][1], a[mt][2], a[mt][3], addr);
            }
#pragma unroll
            for (int mt = 0; mt < 4; mt++)
#pragma unroll
                for (int nt = 0; nt < 2; nt++)
#pragma unroll
                    for (int h = 0; h < 2; h++) {
                        const int jj = nt * 2 + h;
                        mma_16816(acc[mt][jj][0], acc[mt][jj][1], acc[mt][jj][2], acc[mt][jj][3],
                                  a[mt][0], a[mt][1], a[mt][2], a[mt][3],
                                  ball[ks][nt][h], ball[ks][nt][2 + h]);
                    }
        }
    }

    // ---- epilogue: bias add, bf16 stores ------------------------------------
    const int g = lane >> 2;
    const int t = lane & 3;
#pragma unroll
    for (int mt = 0; mt < 4; mt++) {
        const int row0 = m0 + warp_m * 64 + mt * 16 + g;
#pragma unroll
        for (int j = 0; j < 4; j++) {
            const int col = n0 + warp_n * 32 + j * 8 + t * 2;
            const float2 bv = *(const float2*)(bias + col);
            __nv_bfloat162 o0 = __floats2bfloat162_rn(acc[mt][j][0] + bv.x, acc[mt][j][1] + bv.y);
            __nv_bfloat162 o1 = __floats2bfloat162_rn(acc[mt][j][2] + bv.x, acc[mt][j][3] + bv.y);
            *(__nv_bfloat162*)(out + (size_t)row0 * HH + col)       = o0;
            *(__nv_bfloat162*)(out + (size_t)(row0 + 8) * HH + col) = o1;
        }
    }
}

// ---------------------------------------------------------------------------
// Warp-per-row LN statistics of a bf16 activation: st[row] = {mu, rs}.
// ---------------------------------------------------------------------------
__global__ __launch_bounds__(256)
void ln_stats(const __nv_bfloat16* __restrict__ in, float2* __restrict__ st)
{
    const int row  = (blockIdx.x * 256 + threadIdx.x) >> 5;
    const int lane = threadIdx.x & 31;
    const __nv_bfloat16* p = in + (size_t)row * HH;

    float s = 0.f, sq = 0.f;
#pragma unroll
    for (int i = 0; i < 3; i++) {
        const uint2 raw = *(const uint2*)(p + (lane + 32 * i) * 4);
        const float2 f0 = __bfloat1622float2(*(const __nv_bfloat162*)&raw.x);
        const float2 f1 = __bfloat1622float2(*(const __nv_bfloat162*)&raw.y);
        s  += f0.x + f0.y + f1.x + f1.y;
        sq += f0.x * f0.x + f0.y * f0.y + f1.x * f1.x + f1.y * f1.y;
    }
#pragma unroll
    for (int off = 16; off > 0; off >>= 1) {
        s  += __shfl_xor_sync(0xffffffffu, s,  off);
        sq += __shfl_xor_sync(0xffffffffu, sq, off);
    }
    if (lane == 0) {
        const float mu = s * (1.f / HH);
        st[row] = make_float2(mu, rsqrtf(sq * (1.f / HH) - mu * mu + 1e-5f));
    }
}

// ---------------------------------------------------------------------------
// Warp-per-row LayerNorm + ReLU + linear(384->1) + exp, bf16 in.
// ---------------------------------------------------------------------------
__global__ __launch_bounds__(256)
void ln_linear_exp(const __nv_bfloat16* __restrict__ in, const float* __restrict__ g,
                   const float* __restrict__ beta, const float* __restrict__ wl,
                   const float* __restrict__ bl, float* __restrict__ pred)
{
    const int row  = (blockIdx.x * 256 + threadIdx.x) >> 5;
    const int lane = threadIdx.x & 31;
    const __nv_bfloat16* p = in + (size_t)row * HH;

    float v[3][4];
    float s = 0.f, sq = 0.f;
#pragma unroll
    for (int i = 0; i < 3; i++) {
        const uint2 raw = *(const uint2*)(p + (lane + 32 * i) * 4);
        const float2 f0 = __bfloat1622float2(*(const __nv_bfloat162*)&raw.x);
        const float2 f1 = __bfloat1622float2(*(const __nv_bfloat162*)&raw.y);
        v[i][0] = f0.x; v[i][1] = f0.y; v[i][2] = f1.x; v[i][3] = f1.y;
#pragma unroll
        for (int q = 0; q < 4; q++) { s += v[i][q]; sq += v[i][q] * v[i][q]; }
    }
#pragma unroll
    for (int off = 16; off > 0; off >>= 1) {
        s  += __shfl_xor_sync(0xffffffffu, s,  off);
        sq += __shfl_xor_sync(0xffffffffu, sq, off);
    }
    const float mu = s * (1.f / HH);
    const float rs = rsqrtf(sq * (1.f / HH) - mu * mu + 1e-5f);

    float d = 0.f;
#pragma unroll
    for (int i = 0; i < 3; i++) {
        const int c = (lane + 32 * i) * 4;
        const float4 gv = *(const float4*)(g + c);
        const float4 bv = *(const float4*)(beta + c);
        const float4 wv = *(const float4*)(wl + c);
        d += fmaxf(0.f, (v[i][0] - mu) * rs * gv.x + bv.x) * wv.x;
        d += fmaxf(0.f, (v[i][1] - mu) * rs * gv.y + bv.y) * wv.y;
        d += fmaxf(0.f, (v[i][2] - mu) * rs * gv.z + bv.z) * wv.z;
        d += fmaxf(0.f, (v[i][3] - mu) * rs * gv.w + bv.w) * wv.w;
    }
#pragma unroll
    for (int off = 16; off > 0; off >>= 1)
        d += __shfl_xor_sync(0xffffffffu, d, off);
    if (lane == 0) pred[row] = expf(d + bl[0]);
}

// ---------------------------------------------------------------------------
// Tiled weight transpose: wt[n][kc] = bf16(w[kc][n]). Coalesced both ways.
// grid (KDIM/32, HH/32, 2), block (32, 8).
// ---------------------------------------------------------------------------
__global__ void wtrans_tile(const float* __restrict__ w1, __nv_bfloat16* __restrict__ wt1,
                            const float* __restrict__ w2, __nv_bfloat16* __restrict__ wt2)
{
    __shared__ float tile[32][33];
    const float* w = blockIdx.z ? w2 : w1;
    __nv_bfloat16* wt = blockIdx.z ? wt2 : wt1;
    const int kc0 = blockIdx.x * 32;
    const int n0  = blockIdx.y * 32;
    const int tx = threadIdx.x, ty = threadIdx.y;
#pragma unroll
    for (int r = ty; r < 32; r += 8)
        tile[r][tx] = w[(size_t)(kc0 + r) * HH + n0 + tx];
    __syncthreads();
#pragma unroll
    for (int r = ty; r < 32; r += 8)
        wt[(size_t)(n0 + r) * KDIM + kc0 + tx] = __float2bfloat16(tile[tx][r]);
}

// ---------------------------------------------------------------------------
__global__ __launch_bounds__(1024)
void cumsum_kernel(const int* __restrict__ dur, int* __restrict__ cum)
{
    __shared__ int buf[SS];
    const int b = blockIdx.x, tid = threadIdx.x;
    buf[tid] = dur[b * SS + tid];
    __syncthreads();
#pragma unroll
    for (int off = 1; off < SS; off <<= 1) {
        int t = buf[tid];
        int u = (tid >= off) ? buf[tid - off] : 0;
        __syncthreads();
        buf[tid] = t + u;
        __syncthreads();
    }
    cum[b * SS + tid] = buf[tid];
}

__global__ __launch_bounds__(256)
void gather_kernel(const float* __restrict__ x, const int* __restrict__ cum,
                   float* __restrict__ out)
{
    const int gw   = (blockIdx.x * 256 + threadIdx.x) >> 5;
    const int lane = threadIdx.x & 31;
    const int b = gw / MAX_OUT_T;
    const int t = gw - b * MAX_OUT_T;

    const int* c = cum + b * SS;
    const bool valid = t < c[SS - 1];
    int lo = 0, hi = SS;
    while (lo < hi) {
        int mid = (lo + hi) >> 1;
        if (c[mid] <= t) lo = mid + 1; else hi = mid;
    }
    const int src = min(lo, SS - 1);

    const float4* xin = (const float4*)(x + ((size_t)b * SS + src) * CC);
    float4* o = (float4*)(out + (size_t)gw * CC);
    const float4 z = make_float4(0.f, 0.f, 0.f, 0.f);
#pragma unroll
    for (int i = 0; i < 3; i++)
        o[lane + i * 32] = valid ? xin[lane + i * 32] : z;
}

// ---------------------------------------------------------------------------
extern "C" void kernel_launch(void* const* d_in, const int* in_sizes, int n_in,
                              void* d_out, int out_size)
{
    const float* x     = (const float*)d_in[0];
    const int*   dur   = (const int*)  d_in[1];
    const float* w1    = (const float*)d_in[2];
    const float* b1    = (const float*)d_in[3];
    const float* g1    = (const float*)d_in[4];
    const float* beta1 = (const float*)d_in[5];
    const float* w2    = (const float*)d_in[6];
    const float* b2    = (const float*)d_in[7];
    const float* g2    = (const float*)d_in[8];
    const float* beta2 = (const float*)d_in[9];
    const float* wl    = (const float*)d_in[10];
    const float* bl    = (const float*)d_in[11];
    float* out = (float*)d_out;

    __nv_bfloat16 *wt1, *wt2, *t1b, *t2b;
    float2* stats;
    int* cum;
    cudaGetSymbolAddress((void**)&wt1,   g_wt1);
    cudaGetSymbolAddress((void**)&wt2,   g_wt2);
    cudaGetSymbolAddress((void**)&t1b,   g_t1b);
    cudaGetSymbolAddress((void**)&t2b,   g_t2b);
    cudaGetSymbolAddress((void**)&stats, g_stats);
    cudaGetSymbolAddress((void**)&cum,   g_cum);

    cudaFuncSetAttribute(conv_gemm_fused<0>, cudaFuncAttributeMaxDynamicSharedMemorySize, GEMM_SMEM);
    cudaFuncSetAttribute(conv_gemm_fused<1>, cudaFuncAttributeMaxDynamicSharedMemorySize, GEMM_SMEM);

    static cudaStream_t s2 = nullptr, s3 = nullptr;
    static cudaEvent_t  ev_fork = nullptr, ev_wt = nullptr, ev_join = nullptr, ev_s3 = nullptr;
    if (s2 == nullptr) {
        cudaStreamCreateWithFlags(&s2, cudaStreamNonBlocking);
        cudaStreamCreateWithFlags(&s3, cudaStreamNonBlocking);
        cudaEventCreateWithFlags(&ev_fork, cudaEventDisableTiming);
        cudaEventCreateWithFlags(&ev_wt,   cudaEventDisableTiming);
        cudaEventCreateWithFlags(&ev_join, cudaEventDisableTiming);
        cudaEventCreateWithFlags(&ev_s3,   cudaEventDisableTiming);
    }

    // ---- fork ---------------------------------------------------------------
    cudaEventRecord(ev_fork, (cudaStream_t)0);
    cudaStreamWaitEvent(s2, ev_fork, 0);
    cudaStreamWaitEvent(s3, ev_fork, 0);

    // ---- s2: weight transpose + length regulation ---------------------------
    {
        dim3 wg(KDIM / 32, HH / 32, 2);    // (36, 12, 2)
        wtrans_tile<<<wg, dim3(32, 8), 0, s2>>>(w1, wt1, w2, wt2);
    }
    cudaEventRecord(ev_wt, s2);
    cumsum_kernel<<<BB, SS, 0, s2>>>(dur, cum);
    gather_kernel<<<(BB * MAX_OUT_T) / 8, 256, 0, s2>>>(x, cum, out);
    cudaEventRecord(ev_join, s2);

    // ---- predictor chain, two independent M-halves --------------------------
    const dim3 half_grid(HH / 128, M_HALF / 128);   // (3, 128)
    const size_t HX = (size_t)M_HALF * CC;
    const size_t HT = (size_t)M_HALF * HH;

    // half 0 on the main stream
    cudaStreamWaitEvent((cudaStream_t)0, ev_wt, 0);
    conv_gemm_fused<0><<<half_grid, 256, GEMM_SMEM>>>(
        x, nullptr, nullptr, nullptr, wt1, b1, t1b);
    ln_stats<<<M_HALF / 8, 256>>>(t1b, stats);
    conv_gemm_fused<1><<<half_grid, 256, GEMM_SMEM>>>(
        t1b, stats, g1, beta1, wt2, b2, t2b);
    ln_linear_exp<<<M_HALF / 8, 256>>>(t2b, g2, beta2, wl, bl, out + PRED_OFFSET);

    // half 1 on s3
    cudaStreamWaitEvent(s3, ev_wt, 0);
    conv_gemm_fused<0><<<half_grid, 256, GEMM_SMEM, s3>>>(
        x + HX, nullptr, nullptr, nullptr, wt1, b1, t1b + HT);
    ln_stats<<<M_HALF / 8, 256, 0, s3>>>(t1b + HT, stats + M_HALF);
    conv_gemm_fused<1><<<half_grid, 256, GEMM_SMEM, s3>>>(
        t1b + HT, stats + M_HALF, g1, beta1, wt2, b2, t2b + HT);
    ln_linear_exp<<<M_HALF / 8, 256, 0, s3>>>(t2b + HT, g2, beta2, wl, bl,
                                              out + PRED_OFFSET + M_HALF);
    cudaEventRecord(ev_s3, s3);

    // ---- join ----------------------------------------------------------------
    cudaStreamWaitEvent((cudaStream_t)0, ev_join, 0);
    cudaStreamWaitEvent((cudaStream_t)0, ev_s3, 0);
}

// round 15
// speedup vs baseline: 1.1117x; 1.1117x over previous
#include <cuda_runtime.h>
#include <cuda_bf16.h>
#include <math.h>
#include <stdint.h>

#define BB 32
#define SS 1024
#define CC 384
#define HH 384
#define MAX_OUT_T 3072
#define M_TOTAL (BB*SS)          // 32768
#define M_HALF  (M_TOTAL/2)      // 16384 (multiple of SS -> halo-safe split)
#define KDIM (3*CC)              // 1152
#define PRED_OFFSET ((size_t)BB*MAX_OUT_T*CC)

// ---------------- scratch (static device globals: allocation-free) ----------
__device__ __nv_bfloat16 g_xb  [(size_t)M_TOTAL*CC];
__device__ __nv_bfloat16 g_h1b [(size_t)M_TOTAL*HH];
__device__ __nv_bfloat16 g_wt1 [(size_t)HH*KDIM];
__device__ __nv_bfloat16 g_wt2 [(size_t)HH*KDIM];
__device__ __nv_bfloat16 g_t1b [(size_t)M_TOTAL*HH];
__device__ __nv_bfloat16 g_t2b [(size_t)M_TOTAL*HH];
__device__ int   g_cum[BB*SS];

// ---------------- PTX helpers (baseline PTX only) ----------------------------
__device__ __forceinline__ uint32_t smem_u32(const void* p) {
    uint32_t a;
    asm("{ .reg .u64 t; cvta.to.shared.u64 t, %1; cvt.u32.u64 %0, t; }" : "=r"(a) : "l"(p));
    return a;
}
__device__ __forceinline__ void cp_async16(uint32_t saddr, const void* gptr, uint32_t sz) {
    asm volatile("cp.async.cg.shared.global [%0], [%1], 16, %2;"
                 :: "r"(saddr), "l"(gptr), "r"(sz) : "memory");
}
__device__ __forceinline__ void cp_commit() {
    asm volatile("cp.async.commit_group;" ::: "memory");
}
template <int N>
__device__ __forceinline__ void cp_wait() {
    asm volatile("cp.async.wait_group %0;" :: "n"(N) : "memory");
}
__device__ __forceinline__ void ldmatrix_x4(uint32_t& r0, uint32_t& r1, uint32_t& r2,
                                            uint32_t& r3, uint32_t addr) {
    asm volatile("ldmatrix.sync.aligned.m8n8.x4.shared.b16 {%0,%1,%2,%3}, [%4];"
                 : "=r"(r0), "=r"(r1), "=r"(r2), "=r"(r3) : "r"(addr));
}
__device__ __forceinline__ void mma_16816(float& d0, float& d1, float& d2, float& d3,
                                          uint32_t a0, uint32_t a1, uint32_t a2, uint32_t a3,
                                          uint32_t b0, uint32_t b1) {
    asm volatile("mma.sync.aligned.m16n8k16.row.col.f32.bf16.bf16.f32 "
                 "{%0,%1,%2,%3}, {%4,%5,%6,%7}, {%8,%9}, {%0,%1,%2,%3};"
                 : "+f"(d0), "+f"(d1), "+f"(d2), "+f"(d3)
                 : "r"(a0), "r"(a1), "r"(a2), "r"(a3), "r"(b0), "r"(b1));
}

// ---------------------------------------------------------------------------
// Conv-as-GEMM with 3-tap A reuse (round-12 exact structure).
//   18 MMA-steps s=(j,k), j=channel chunk 0..5, k=conv tap 0..2.
//   A: per chunk j, ONE 130-row region shared by all 3 taps (+k row offset).
//   B: one 128x64 tile per step, 4-slot ring, loaded 3 steps ahead.
//   One commit group per step; cp.async.wait_group 2. All fills via cp.async.
// ---------------------------------------------------------------------------
#define NSTEPS 18
#define A_STRIDE 17408                    // 130 rows x 128 B, padded
#define B_BASE   (2*A_STRIDE)             // 34816
#define TILE_B   16384
#define GEMM_SMEM (B_BASE + 4*TILE_B)     // 100352 -> 2 CTAs/SM

__global__ __launch_bounds__(256, 2)
void conv_gemm_mma(const __nv_bfloat16* __restrict__ A,
                   const __nv_bfloat16* __restrict__ Wt,
                   const float* __restrict__ bias,
                   __nv_bfloat16* __restrict__ out)
{
    extern __shared__ __align__(1024) char smem[];
    const uint32_t sbase = smem_u32(smem);
    const int tid  = threadIdx.x;
    const int wid  = tid >> 5;
    const int lane = tid & 31;
    const int warp_m = wid & 1;
    const int warp_n = wid >> 1;
    const int n0 = blockIdx.x * 128;
    const int m0 = blockIdx.y * 128;

    const int lrow = tid >> 3;              // 0..31
    const int lcx  = (tid & 7) * 16;

    auto load_A = [&](int j) {
        const uint32_t abase_w = sbase + (uint32_t)((j & 1) * A_STRIDE);
        const int c0   = j * 64;
        const int seq0 = m0 & ~(SS - 1);
#pragma unroll
        for (int i = 0; i < 5; i++) {
            const int rr = lrow + 32 * i;            // 0..159
            if (rr < 130) {
                const int xr = m0 - 1 + rr;
                const bool valid = (xr >= seq0) && (xr < seq0 + SS);
                uint32_t off = (uint32_t)(rr * 128 + lcx);
                uint32_t sw  = off ^ ((off >> 3) & 0x70);
                const char* gp = valid
                    ? ((const char*)A + ((size_t)xr * CC + c0) * 2 + lcx)
                    : (const char*)A;
                cp_async16(abase_w + sw, gp, valid ? 16u : 0u);
            }
        }
    };
    auto load_B = [&](int b) {
        const int j = b / 3, k = b - 3 * j;
        const int kc0 = k * CC + j * 64;
        const uint32_t bbase_w = sbase + B_BASE + (uint32_t)((b & 3) * TILE_B);
#pragma unroll
        for (int i = 0; i < 4; i++) {
            const int row = lrow + 32 * i;
            uint32_t off = (uint32_t)(row * 128 + lcx);
            uint32_t sw  = off ^ ((off >> 3) & 0x70);
            const char* gp = (const char*)Wt + ((size_t)(n0 + row) * KDIM + kc0) * 2 + lcx;
            cp_async16(bbase_w + sw, gp, 16u);
        }
    };

    float acc[4][4][4];
#pragma unroll
    for (int i = 0; i < 4; i++)
#pragma unroll
        for (int j = 0; j < 4; j++)
#pragma unroll
            for (int q = 0; q < 4; q++) acc[i][j][q] = 0.f;

    const int fr_row = ((lane >> 3) & 1) * 8 + (lane & 7);
    const int fr_kb  = (lane >> 4) * 16;
    const uint32_t cxor = (uint32_t)((fr_row & 7) << 4);                 // B swizzle
    const uint32_t a_row_base = (uint32_t)((warp_m * 64 + fr_row) * 128);
    const uint32_t b_row_base = (uint32_t)((warp_n * 32 + fr_row) * 128);

    // prologue: g0={A0,B0}, g1={B1}, g2={B2}
    load_A(0); load_B(0); cp_commit();
    load_B(1); cp_commit();
    load_B(2); cp_commit();

    for (int s = 0; s < NSTEPS; ++s) {
        const int j = s / 3;
        const int k = s - 3 * j;

        cp_wait<2>();
        __syncthreads();

        if (s <= NSTEPS - 4) load_B(s + 3);
        if (k == 0 && j < 5)  load_A(j + 1);
        cp_commit();

        const uint32_t sa = sbase + (uint32_t)((j & 1) * A_STRIDE) + (uint32_t)(k * 128);
        const uint32_t sb = sbase + B_BASE + (uint32_t)((s & 3) * TILE_B);
        const uint32_t cxork = (uint32_t)(((fr_row + k) & 7) << 4);      // A swizzle (+k rows)

        uint32_t ball[4][2][4];
#pragma unroll
        for (int ks = 0; ks < 4; ks++) {
            const uint32_t col = ((uint32_t)(ks * 32 + fr_kb)) ^ cxor;
#pragma unroll
            for (int nt = 0; nt < 2; nt++) {
                const uint32_t addr = sb + b_row_base + (uint32_t)(nt * 2048) + col;
                ldmatrix_x4(ball[ks][nt][0], ball[ks][nt][1], ball[ks][nt][2], ball[ks][nt][3], addr);
            }
        }

#pragma unroll
        for (int ks = 0; ks < 4; ks++) {
            const uint32_t col = ((uint32_t)(ks * 32 + fr_kb)) ^ cxork;
            uint32_t a[4][4];
#pragma unroll
            for (int mt = 0; mt < 4; mt++) {
                const uint32_t addr = sa + a_row_base + (uint32_t)(mt * 2048) + col;
                ldmatrix_x4(a[mt][0], a[mt][1], a[mt][2], a[mt][3], addr);
            }
#pragma unroll
            for (int mt = 0; mt < 4; mt++)
#pragma unroll
                for (int nt = 0; nt < 2; nt++)
#pragma unroll
                    for (int h = 0; h < 2; h++) {
                        const int jj = nt * 2 + h;
                        mma_16816(acc[mt][jj][0], acc[mt][jj][1], acc[mt][jj][2], acc[mt][jj][3],
                                  a[mt][0], a[mt][1], a[mt][2], a[mt][3],
                                  ball[ks][nt][h], ball[ks][nt][2 + h]);
                    }
        }
    }

    // ---- epilogue: bias add, bf16 stores ------------------------------------
    const int g = lane >> 2;
    const int t = lane & 3;
#pragma unroll
    for (int mt = 0; mt < 4; mt++) {
        const int row0 = m0 + warp_m * 64 + mt * 16 + g;
#pragma unroll
        for (int j = 0; j < 4; j++) {
            const int col = n0 + warp_n * 32 + j * 8 + t * 2;
            const float2 bv = *(const float2*)(bias + col);
            __nv_bfloat162 o0 = __floats2bfloat162_rn(acc[mt][j][0] + bv.x, acc[mt][j][1] + bv.y);
            __nv_bfloat162 o1 = __floats2bfloat162_rn(acc[mt][j][2] + bv.x, acc[mt][j][3] + bv.y);
            *(__nv_bfloat162*)(out + (size_t)row0 * HH + col)       = o0;
            *(__nv_bfloat162*)(out + (size_t)(row0 + 8) * HH + col) = o1;
        }
    }
}

// ---------------------------------------------------------------------------
// Warp-per-row LayerNorm + ReLU, bf16 in -> bf16 out. fp32 math.
// ---------------------------------------------------------------------------
__global__ __launch_bounds__(256)
void ln_relu_bf16(const __nv_bfloat16* __restrict__ in, const float* __restrict__ g,
                  const float* __restrict__ beta, __nv_bfloat16* __restrict__ outb)
{
    const int row  = (blockIdx.x * 256 + threadIdx.x) >> 5;
    const int lane = threadIdx.x & 31;
    const __nv_bfloat16* p = in + (size_t)row * HH;

    float v[3][4];
    float s = 0.f, sq = 0.f;
#pragma unroll
    for (int i = 0; i < 3; i++) {
        const uint2 raw = *(const uint2*)(p + (lane + 32 * i) * 4);
        const float2 f0 = __bfloat1622float2(*(const __nv_bfloat162*)&raw.x);
        const float2 f1 = __bfloat1622float2(*(const __nv_bfloat162*)&raw.y);
        v[i][0] = f0.x; v[i][1] = f0.y; v[i][2] = f1.x; v[i][3] = f1.y;
#pragma unroll
        for (int q = 0; q < 4; q++) { s += v[i][q]; sq += v[i][q] * v[i][q]; }
    }
#pragma unroll
    for (int off = 16; off > 0; off >>= 1) {
        s  += __shfl_xor_sync(0xffffffffu, s,  off);
        sq += __shfl_xor_sync(0xffffffffu, sq, off);
    }
    const float mu = s * (1.f / HH);
    const float rs = rsqrtf(sq * (1.f / HH) - mu * mu + 1e-5f);

    __nv_bfloat16* op = outb + (size_t)row * HH;
#pragma unroll
    for (int i = 0; i < 3; i++) {
        const int c = (lane + 32 * i) * 4;
        const float4 gv = *(const float4*)(g + c);
        const float4 bv = *(const float4*)(beta + c);
        float o0 = fmaxf(0.f, (v[i][0] - mu) * rs * gv.x + bv.x);
        float o1 = fmaxf(0.f, (v[i][1] - mu) * rs * gv.y + bv.y);
        float o2 = fmaxf(0.f, (v[i][2] - mu) * rs * gv.z + bv.z);
        float o3 = fmaxf(0.f, (v[i][3] - mu) * rs * gv.w + bv.w);
        __nv_bfloat162 p0 = __floats2bfloat162_rn(o0, o1);
        __nv_bfloat162 p1 = __floats2bfloat162_rn(o2, o3);
        uint2 u; u.x = *(uint32_t*)&p0; u.y = *(uint32_t*)&p1;
        *(uint2*)(op + c) = u;
    }
}

// ---------------------------------------------------------------------------
// Warp-per-row LayerNorm + ReLU + linear(384->1) + exp, bf16 in.
// ---------------------------------------------------------------------------
__global__ __launch_bounds__(256)
void ln_linear_exp(const __nv_bfloat16* __restrict__ in, const float* __restrict__ g,
                   const float* __restrict__ beta, const float* __restrict__ wl,
                   const float* __restrict__ bl, float* __restrict__ pred)
{
    const int row  = (blockIdx.x * 256 + threadIdx.x) >> 5;
    const int lane = threadIdx.x & 31;
    const __nv_bfloat16* p = in + (size_t)row * HH;

    float v[3][4];
    float s = 0.f, sq = 0.f;
#pragma unroll
    for (int i = 0; i < 3; i++) {
        const uint2 raw = *(const uint2*)(p + (lane + 32 * i) * 4);
        const float2 f0 = __bfloat1622float2(*(const __nv_bfloat162*)&raw.x);
        const float2 f1 = __bfloat1622float2(*(const __nv_bfloat162*)&raw.y);
        v[i][0] = f0.x; v[i][1] = f0.y; v[i][2] = f1.x; v[i][3] = f1.y;
#pragma unroll
        for (int q = 0; q < 4; q++) { s += v[i][q]; sq += v[i][q] * v[i][q]; }
    }
#pragma unroll
    for (int off = 16; off > 0; off >>= 1) {
        s  += __shfl_xor_sync(0xffffffffu, s,  off);
        sq += __shfl_xor_sync(0xffffffffu, sq, off);
    }
    const float mu = s * (1.f / HH);
    const float rs = rsqrtf(sq * (1.f / HH) - mu * mu + 1e-5f);

    float d = 0.f;
#pragma unroll
    for (int i = 0; i < 3; i++) {
        const int c = (lane + 32 * i) * 4;
        const float4 gv = *(const float4*)(g + c);
        const float4 bv = *(const float4*)(beta + c);
        const float4 wv = *(const float4*)(wl + c);
        d += fmaxf(0.f, (v[i][0] - mu) * rs * gv.x + bv.x) * wv.x;
        d += fmaxf(0.f, (v[i][1] - mu) * rs * gv.y + bv.y) * wv.y;
        d += fmaxf(0.f, (v[i][2] - mu) * rs * gv.z + bv.z) * wv.z;
        d += fmaxf(0.f, (v[i][3] - mu) * rs * gv.w + bv.w) * wv.w;
    }
#pragma unroll
    for (int off = 16; off > 0; off >>= 1)
        d += __shfl_xor_sync(0xffffffffu, d, off);
    if (lane == 0) pred[row] = expf(d + bl[0]);
}

// ---------------------------------------------------------------------------
__global__ __launch_bounds__(256)
void f32_to_bf16(const float* __restrict__ x, __nv_bfloat16* __restrict__ y)
{
    const size_t i = ((size_t)blockIdx.x * 256 + threadIdx.x) * 4;
    float4 v = *(const float4*)(x + i);
    __nv_bfloat162 p0 = __floats2bfloat162_rn(v.x, v.y);
    __nv_bfloat162 p1 = __floats2bfloat162_rn(v.z, v.w);
    uint2 o;
    o.x = *(uint32_t*)&p0; o.y = *(uint32_t*)&p1;
    *(uint2*)(y + i) = o;
}

// ---------------------------------------------------------------------------
// Tiled weight transpose: wt[n][kc] = bf16(w[kc][n]). Coalesced both ways.
// grid (KDIM/32, HH/32), block (32, 8). One weight matrix per launch.
// ---------------------------------------------------------------------------
__global__ void wtrans_tile(const float* __restrict__ w, __nv_bfloat16* __restrict__ wt)
{
    __shared__ float tile[32][33];
    const int kc0 = blockIdx.x * 32;
    const int n0  = blockIdx.y * 32;
    const int tx = threadIdx.x, ty = threadIdx.y;
#pragma unroll
    for (int r = ty; r < 32; r += 8)
        tile[r][tx] = w[(size_t)(kc0 + r) * HH + n0 + tx];
    __syncthreads();
#pragma unroll
    for (int r = ty; r < 32; r += 8)
        wt[(size_t)(n0 + r) * KDIM + kc0 + tx] = __float2bfloat16(tile[tx][r]);
}

// ---------------------------------------------------------------------------
__global__ __launch_bounds__(1024)
void cumsum_kernel(const int* __restrict__ dur, int* __restrict__ cum)
{
    __shared__ int buf[SS];
    const int b = blockIdx.x, tid = threadIdx.x;
    buf[tid] = dur[b * SS + tid];
    __syncthreads();
#pragma unroll
    for (int off = 1; off < SS; off <<= 1) {
        int t = buf[tid];
        int u = (tid >= off) ? buf[tid - off] : 0;
        __syncthreads();
        buf[tid] = t + u;
        __syncthreads();
    }
    cum[b * SS + tid] = buf[tid];
}

__global__ __launch_bounds__(256)
void gather_kernel(const float* __restrict__ x, const int* __restrict__ cum,
                   float* __restrict__ out)
{
    const int gw   = (blockIdx.x * 256 + threadIdx.x) >> 5;
    const int lane = threadIdx.x & 31;
    const int b = gw / MAX_OUT_T;
    const int t = gw - b * MAX_OUT_T;

    const int* c = cum + b * SS;
    const bool valid = t < c[SS - 1];
    int lo = 0, hi = SS;
    while (lo < hi) {
        int mid = (lo + hi) >> 1;
        if (c[mid] <= t) lo = mid + 1; else hi = mid;
    }
    const int src = min(lo, SS - 1);

    const float4* xin = (const float4*)(x + ((size_t)b * SS + src) * CC);
    float4* o = (float4*)(out + (size_t)gw * CC);
    const float4 z = make_float4(0.f, 0.f, 0.f, 0.f);
#pragma unroll
    for (int i = 0; i < 3; i++)
        o[lane + i * 32] = valid ? xin[lane + i * 32] : z;
}

// ---------------------------------------------------------------------------
extern "C" void kernel_launch(void* const* d_in, const int* in_sizes, int n_in,
                              void* d_out, int out_size)
{
    const float* x     = (const float*)d_in[0];
    const int*   dur   = (const int*)  d_in[1];
    const float* w1    = (const float*)d_in[2];
    const float* b1    = (const float*)d_in[3];
    const float* g1    = (const float*)d_in[4];
    const float* beta1 = (const float*)d_in[5];
    const float* w2    = (const float*)d_in[6];
    const float* b2    = (const float*)d_in[7];
    const float* g2    = (const float*)d_in[8];
    const float* beta2 = (const float*)d_in[9];
    const float* wl    = (const float*)d_in[10];
    const float* bl    = (const float*)d_in[11];
    float* out = (float*)d_out;

    __nv_bfloat16 *xb, *h1b, *wt1, *wt2, *t1b, *t2b;
    int* cum;
    cudaGetSymbolAddress((void**)&xb,   g_xb);
    cudaGetSymbolAddress((void**)&h1b,  g_h1b);
    cudaGetSymbolAddress((void**)&wt1,  g_wt1);
    cudaGetSymbolAddress((void**)&wt2,  g_wt2);
    cudaGetSymbolAddress((void**)&t1b,  g_t1b);
    cudaGetSymbolAddress((void**)&t2b,  g_t2b);
    cudaGetSymbolAddress((void**)&cum,  g_cum);

    cudaFuncSetAttribute(conv_gemm_mma, cudaFuncAttributeMaxDynamicSharedMemorySize, GEMM_SMEM);

    static cudaStream_t s2 = nullptr, s3 = nullptr;
    static cudaEvent_t  ev_fork = nullptr, ev_wt1 = nullptr, ev_wt2 = nullptr,
                        ev_join = nullptr, ev_s3 = nullptr;
    if (s2 == nullptr) {
        cudaStreamCreateWithFlags(&s2, cudaStreamNonBlocking);
        cudaStreamCreateWithFlags(&s3, cudaStreamNonBlocking);
        cudaEventCreateWithFlags(&ev_fork, cudaEventDisableTiming);
        cudaEventCreateWithFlags(&ev_wt1,  cudaEventDisableTiming);
        cudaEventCreateWithFlags(&ev_wt2,  cudaEventDisableTiming);
        cudaEventCreateWithFlags(&ev_join, cudaEventDisableTiming);
        cudaEventCreateWithFlags(&ev_s3,   cudaEventDisableTiming);
    }

    // ---- fork ---------------------------------------------------------------
    cudaEventRecord(ev_fork, (cudaStream_t)0);
    cudaStreamWaitEvent(s2, ev_fork, 0);
    cudaStreamWaitEvent(s3, ev_fork, 0);

    // ---- s2: weight transposes (wt1 gated early) + length regulation --------
    {
        dim3 wg(KDIM / 32, HH / 32);       // (36, 12)
        wtrans_tile<<<wg, dim3(32, 8), 0, s2>>>(w1, wt1);
        cudaEventRecord(ev_wt1, s2);
        wtrans_tile<<<wg, dim3(32, 8), 0, s2>>>(w2, wt2);
        cudaEventRecord(ev_wt2, s2);
    }
    cumsum_kernel<<<BB, SS, 0, s2>>>(dur, cum);
    gather_kernel<<<(BB * MAX_OUT_T) / 8, 256, 0, s2>>>(x, cum, out);
    cudaEventRecord(ev_join, s2);

    // ---- predictor chain, two independent M-halves --------------------------
    const dim3 half_grid(HH / 128, M_HALF / 128);   // (3, 128)
    const size_t HX = (size_t)M_HALF * CC;
    const size_t HT = (size_t)M_HALF * HH;

    // half 0 on the main stream
    f32_to_bf16<<<(M_HALF * CC) / 1024, 256>>>(x, xb);
    cudaStreamWaitEvent((cudaStream_t)0, ev_wt1, 0);
    conv_gemm_mma<<<half_grid, 256, GEMM_SMEM>>>(xb, wt1, b1, t1b);
    ln_relu_bf16<<<M_HALF / 8, 256>>>(t1b, g1, beta1, h1b);
    cudaStreamWaitEvent((cudaStream_t)0, ev_wt2, 0);
    conv_gemm_mma<<<half_grid, 256, GEMM_SMEM>>>(h1b, wt2, b2, t2b);
    ln_linear_exp<<<M_HALF / 8, 256>>>(t2b, g2, beta2, wl, bl, out + PRED_OFFSET);

    // half 1 on s3
    f32_to_bf16<<<(M_HALF * CC) / 1024, 256, 0, s3>>>(x + HX, xb + HX);
    cudaStreamWaitEvent(s3, ev_wt1, 0);
    conv_gemm_mma<<<half_grid, 256, GEMM_SMEM, s3>>>(xb + HX, wt1, b1, t1b + HT);
    ln_relu_bf16<<<M_HALF / 8, 256, 0, s3>>>(t1b + HT, g1, beta1, h1b + HT);
    cudaStreamWaitEvent(s3, ev_wt2, 0);
    conv_gemm_mma<<<half_grid, 256, GEMM_SMEM, s3>>>(h1b + HT, wt2, b2, t2b + HT);
    ln_linear_exp<<<M_HALF / 8, 256, 0, s3>>>(t2b + HT, g2, beta2, wl, bl,
                                              out + PRED_OFFSET + M_HALF);
    cudaEventRecord(ev_s3, s3);

    // ---- join ----------------------------------------------------------------
    cudaStreamWaitEvent((cudaStream_t)0, ev_join, 0);
    cudaStreamWaitEvent((cudaStream_t)0, ev_s3, 0);
}

// round 16
// speedup vs baseline: 1.1182x; 1.0058x over previous
#include <cuda_runtime.h>
#include <cuda_bf16.h>
#include <math.h>
#include <stdint.h>

#define BB 32
#define SS 1024
#define CC 384
#define HH 384
#define MAX_OUT_T 3072
#define M_TOTAL (BB*SS)          // 32768
#define M_HALF  (M_TOTAL/2)      // 16384 (multiple of SS -> halo-safe split)
#define KDIM (3*CC)              // 1152
#define PRED_OFFSET ((size_t)BB*MAX_OUT_T*CC)

// ---------------- scratch (static device globals: allocation-free) ----------
__device__ __nv_bfloat16 g_xb  [(size_t)M_TOTAL*CC];
__device__ __nv_bfloat16 g_h1b [(size_t)M_TOTAL*HH];
__device__ __nv_bfloat16 g_wt1 [(size_t)HH*KDIM];
__device__ __nv_bfloat16 g_wt2 [(size_t)HH*KDIM];
__device__ __nv_bfloat16 g_t1b [(size_t)M_TOTAL*HH];
__device__ __nv_bfloat16 g_t2b [(size_t)M_TOTAL*HH];
__device__ int   g_cum[BB*SS];

// ---------------- PTX helpers (baseline PTX only) ----------------------------
__device__ __forceinline__ uint32_t smem_u32(const void* p) {
    uint32_t a;
    asm("{ .reg .u64 t; cvta.to.shared.u64 t, %1; cvt.u32.u64 %0, t; }" : "=r"(a) : "l"(p));
    return a;
}
__device__ __forceinline__ void cp_async16(uint32_t saddr, const void* gptr, uint32_t sz) {
    asm volatile("cp.async.cg.shared.global [%0], [%1], 16, %2;"
                 :: "r"(saddr), "l"(gptr), "r"(sz) : "memory");
}
__device__ __forceinline__ void cp_commit() {
    asm volatile("cp.async.commit_group;" ::: "memory");
}
template <int N>
__device__ __forceinline__ void cp_wait() {
    asm volatile("cp.async.wait_group %0;" :: "n"(N) : "memory");
}
__device__ __forceinline__ void ldmatrix_x4(uint32_t& r0, uint32_t& r1, uint32_t& r2,
                                            uint32_t& r3, uint32_t addr) {
    asm volatile("ldmatrix.sync.aligned.m8n8.x4.shared.b16 {%0,%1,%2,%3}, [%4];"
                 : "=r"(r0), "=r"(r1), "=r"(r2), "=r"(r3) : "r"(addr));
}
__device__ __forceinline__ void mma_16816(float& d0, float& d1, float& d2, float& d3,
                                          uint32_t a0, uint32_t a1, uint32_t a2, uint32_t a3,
                                          uint32_t b0, uint32_t b1) {
    asm volatile("mma.sync.aligned.m16n8k16.row.col.f32.bf16.bf16.f32 "
                 "{%0,%1,%2,%3}, {%4,%5,%6,%7}, {%8,%9}, {%0,%1,%2,%3};"
                 : "+f"(d0), "+f"(d1), "+f"(d2), "+f"(d3)
                 : "r"(a0), "r"(a1), "r"(a2), "r"(a3), "r"(b0), "r"(b1));
}

// ---------------------------------------------------------------------------
// Conv-as-GEMM with 3-tap A reuse (round-12 exact structure).
// ---------------------------------------------------------------------------
#define NSTEPS 18
#define A_STRIDE 17408                    // 130 rows x 128 B, padded
#define B_BASE   (2*A_STRIDE)             // 34816
#define TILE_B   16384
#define GEMM_SMEM (B_BASE + 4*TILE_B)     // 100352 -> 2 CTAs/SM

__global__ __launch_bounds__(256, 2)
void conv_gemm_mma(const __nv_bfloat16* __restrict__ A,
                   const __nv_bfloat16* __restrict__ Wt,
                   const float* __restrict__ bias,
                   __nv_bfloat16* __restrict__ out)
{
    extern __shared__ __align__(1024) char smem[];
    const uint32_t sbase = smem_u32(smem);
    const int tid  = threadIdx.x;
    const int wid  = tid >> 5;
    const int lane = tid & 31;
    const int warp_m = wid & 1;
    const int warp_n = wid >> 1;
    const int n0 = blockIdx.x * 128;
    const int m0 = blockIdx.y * 128;

    const int lrow = tid >> 3;              // 0..31
    const int lcx  = (tid & 7) * 16;

    auto load_A = [&](int j) {
        const uint32_t abase_w = sbase + (uint32_t)((j & 1) * A_STRIDE);
        const int c0   = j * 64;
        const int seq0 = m0 & ~(SS - 1);
#pragma unroll
        for (int i = 0; i < 5; i++) {
            const int rr = lrow + 32 * i;            // 0..159
            if (rr < 130) {
                const int xr = m0 - 1 + rr;
                const bool valid = (xr >= seq0) && (xr < seq0 + SS);
                uint32_t off = (uint32_t)(rr * 128 + lcx);
                uint32_t sw  = off ^ ((off >> 3) & 0x70);
                const char* gp = valid
                    ? ((const char*)A + ((size_t)xr * CC + c0) * 2 + lcx)
                    : (const char*)A;
                cp_async16(abase_w + sw, gp, valid ? 16u : 0u);
            }
        }
    };
    auto load_B = [&](int b) {
        const int j = b / 3, k = b - 3 * j;
        const int kc0 = k * CC + j * 64;
        const uint32_t bbase_w = sbase + B_BASE + (uint32_t)((b & 3) * TILE_B);
#pragma unroll
        for (int i = 0; i < 4; i++) {
            const int row = lrow + 32 * i;
            uint32_t off = (uint32_t)(row * 128 + lcx);
            uint32_t sw  = off ^ ((off >> 3) & 0x70);
            const char* gp = (const char*)Wt + ((size_t)(n0 + row) * KDIM + kc0) * 2 + lcx;
            cp_async16(bbase_w + sw, gp, 16u);
        }
    };

    float acc[4][4][4];
#pragma unroll
    for (int i = 0; i < 4; i++)
#pragma unroll
        for (int j = 0; j < 4; j++)
#pragma unroll
            for (int q = 0; q < 4; q++) acc[i][j][q] = 0.f;

    const int fr_row = ((lane >> 3) & 1) * 8 + (lane & 7);
    const int fr_kb  = (lane >> 4) * 16;
    const uint32_t cxor = (uint32_t)((fr_row & 7) << 4);                 // B swizzle
    const uint32_t a_row_base = (uint32_t)((warp_m * 64 + fr_row) * 128);
    const uint32_t b_row_base = (uint32_t)((warp_n * 32 + fr_row) * 128);

    load_A(0); load_B(0); cp_commit();
    load_B(1); cp_commit();
    load_B(2); cp_commit();

    for (int s = 0; s < NSTEPS; ++s) {
        const int j = s / 3;
        const int k = s - 3 * j;

        cp_wait<2>();
        __syncthreads();

        if (s <= NSTEPS - 4) load_B(s + 3);
        if (k == 0 && j < 5)  load_A(j + 1);
        cp_commit();

        const uint32_t sa = sbase + (uint32_t)((j & 1) * A_STRIDE) + (uint32_t)(k * 128);
        const uint32_t sb = sbase + B_BASE + (uint32_t)((s & 3) * TILE_B);
        const uint32_t cxork = (uint32_t)(((fr_row + k) & 7) << 4);      // A swizzle (+k rows)

        uint32_t ball[4][2][4];
#pragma unroll
        for (int ks = 0; ks < 4; ks++) {
            const uint32_t col = ((uint32_t)(ks * 32 + fr_kb)) ^ cxor;
#pragma unroll
            for (int nt = 0; nt < 2; nt++) {
                const uint32_t addr = sb + b_row_base + (uint32_t)(nt * 2048) + col;
                ldmatrix_x4(ball[ks][nt][0], ball[ks][nt][1], ball[ks][nt][2], ball[ks][nt][3], addr);
            }
        }

#pragma unroll
        for (int ks = 0; ks < 4; ks++) {
            const uint32_t col = ((uint32_t)(ks * 32 + fr_kb)) ^ cxork;
            uint32_t a[4][4];
#pragma unroll
            for (int mt = 0; mt < 4; mt++) {
                const uint32_t addr = sa + a_row_base + (uint32_t)(mt * 2048) + col;
                ldmatrix_x4(a[mt][0], a[mt][1], a[mt][2], a[mt][3], addr);
            }
#pragma unroll
            for (int mt = 0; mt < 4; mt++)
#pragma unroll
                for (int nt = 0; nt < 2; nt++)
#pragma unroll
                    for (int h = 0; h < 2; h++) {
                        const int jj = nt * 2 + h;
                        mma_16816(acc[mt][jj][0], acc[mt][jj][1], acc[mt][jj][2], acc[mt][jj][3],
                                  a[mt][0], a[mt][1], a[mt][2], a[mt][3],
                                  ball[ks][nt][h], ball[ks][nt][2 + h]);
                    }
        }
    }

    // ---- epilogue: bias add, bf16 stores ------------------------------------
    const int g = lane >> 2;
    const int t = lane & 3;
#pragma unroll
    for (int mt = 0; mt < 4; mt++) {
        const int row0 = m0 + warp_m * 64 + mt * 16 + g;
#pragma unroll
        for (int j = 0; j < 4; j++) {
            const int col = n0 + warp_n * 32 + j * 8 + t * 2;
            const float2 bv = *(const float2*)(bias + col);
            __nv_bfloat162 o0 = __floats2bfloat162_rn(acc[mt][j][0] + bv.x, acc[mt][j][1] + bv.y);
            __nv_bfloat162 o1 = __floats2bfloat162_rn(acc[mt][j][2] + bv.x, acc[mt][j][3] + bv.y);
            *(__nv_bfloat162*)(out + (size_t)row0 * HH + col)       = o0;
            *(__nv_bfloat162*)(out + (size_t)(row0 + 8) * HH + col) = o1;
        }
    }
}

// ---------------------------------------------------------------------------
// Warp-per-row LayerNorm + ReLU, bf16 in -> bf16 out. fp32 math.
// ---------------------------------------------------------------------------
__global__ __launch_bounds__(256)
void ln_relu_bf16(const __nv_bfloat16* __restrict__ in, const float* __restrict__ g,
                  const float* __restrict__ beta, __nv_bfloat16* __restrict__ outb)
{
    const int row  = (blockIdx.x * 256 + threadIdx.x) >> 5;
    const int lane = threadIdx.x & 31;
    const __nv_bfloat16* p = in + (size_t)row * HH;

    float v[3][4];
    float s = 0.f, sq = 0.f;
#pragma unroll
    for (int i = 0; i < 3; i++) {
        const uint2 raw = *(const uint2*)(p + (lane + 32 * i) * 4);
        const float2 f0 = __bfloat1622float2(*(const __nv_bfloat162*)&raw.x);
        const float2 f1 = __bfloat1622float2(*(const __nv_bfloat162*)&raw.y);
        v[i][0] = f0.x; v[i][1] = f0.y; v[i][2] = f1.x; v[i][3] = f1.y;
#pragma unroll
        for (int q = 0; q < 4; q++) { s += v[i][q]; sq += v[i][q] * v[i][q]; }
    }
#pragma unroll
    for (int off = 16; off > 0; off >>= 1) {
        s  += __shfl_xor_sync(0xffffffffu, s,  off);
        sq += __shfl_xor_sync(0xffffffffu, sq, off);
    }
    const float mu = s * (1.f / HH);
    const float rs = rsqrtf(sq * (1.f / HH) - mu * mu + 1e-5f);

    __nv_bfloat16* op = outb + (size_t)row * HH;
#pragma unroll
    for (int i = 0; i < 3; i++) {
        const int c = (lane + 32 * i) * 4;
        const float4 gv = *(const float4*)(g + c);
        const float4 bv = *(const float4*)(beta + c);
        float o0 = fmaxf(0.f, (v[i][0] - mu) * rs * gv.x + bv.x);
        float o1 = fmaxf(0.f, (v[i][1] - mu) * rs * gv.y + bv.y);
        float o2 = fmaxf(0.f, (v[i][2] - mu) * rs * gv.z + bv.z);
        float o3 = fmaxf(0.f, (v[i][3] - mu) * rs * gv.w + bv.w);
        __nv_bfloat162 p0 = __floats2bfloat162_rn(o0, o1);
        __nv_bfloat162 p1 = __floats2bfloat162_rn(o2, o3);
        uint2 u; u.x = *(uint32_t*)&p0; u.y = *(uint32_t*)&p1;
        *(uint2*)(op + c) = u;
    }
}

// ---------------------------------------------------------------------------
// Warp-per-row LayerNorm + ReLU + linear(384->1) + exp, bf16 in.
// ---------------------------------------------------------------------------
__global__ __launch_bounds__(256)
void ln_linear_exp(const __nv_bfloat16* __restrict__ in, const float* __restrict__ g,
                   const float* __restrict__ beta, const float* __restrict__ wl,
                   const float* __restrict__ bl, float* __restrict__ pred)
{
    const int row  = (blockIdx.x * 256 + threadIdx.x) >> 5;
    const int lane = threadIdx.x & 31;
    const __nv_bfloat16* p = in + (size_t)row * HH;

    float v[3][4];
    float s = 0.f, sq = 0.f;
#pragma unroll
    for (int i = 0; i < 3; i++) {
        const uint2 raw = *(const uint2*)(p + (lane + 32 * i) * 4);
        const float2 f0 = __bfloat1622float2(*(const __nv_bfloat162*)&raw.x);
        const float2 f1 = __bfloat1622float2(*(const __nv_bfloat162*)&raw.y);
        v[i][0] = f0.x; v[i][1] = f0.y; v[i][2] = f1.x; v[i][3] = f1.y;
#pragma unroll
        for (int q = 0; q < 4; q++) { s += v[i][q]; sq += v[i][q] * v[i][q]; }
    }
#pragma unroll
    for (int off = 16; off > 0; off >>= 1) {
        s  += __shfl_xor_sync(0xffffffffu, s,  off);
        sq += __shfl_xor_sync(0xffffffffu, sq, off);
    }
    const float mu = s * (1.f / HH);
    const float rs = rsqrtf(sq * (1.f / HH) - mu * mu + 1e-5f);

    float d = 0.f;
#pragma unroll
    for (int i = 0; i < 3; i++) {
        const int c = (lane + 32 * i) * 4;
        const float4 gv = *(const float4*)(g + c);
        const float4 bv = *(const float4*)(beta + c);
        const float4 wv = *(const float4*)(wl + c);
        d += fmaxf(0.f, (v[i][0] - mu) * rs * gv.x + bv.x) * wv.x;
        d += fmaxf(0.f, (v[i][1] - mu) * rs * gv.y + bv.y) * wv.y;
        d += fmaxf(0.f, (v[i][2] - mu) * rs * gv.z + bv.z) * wv.z;
        d += fmaxf(0.f, (v[i][3] - mu) * rs * gv.w + bv.w) * wv.w;
    }
#pragma unroll
    for (int off = 16; off > 0; off >>= 1)
        d += __shfl_xor_sync(0xffffffffu, d, off);
    if (lane == 0) pred[row] = expf(d + bl[0]);
}

// ---------------------------------------------------------------------------
// fp32 -> bf16 convert, 8 elements/thread (two independent float4 loads).
// ---------------------------------------------------------------------------
__global__ __launch_bounds__(256)
void f32_to_bf16(const float* __restrict__ x, __nv_bfloat16* __restrict__ y)
{
    const size_t i = ((size_t)blockIdx.x * 256 + threadIdx.x) * 8;
    const float4 v0 = *(const float4*)(x + i);
    const float4 v1 = *(const float4*)(x + i + 4);
    __nv_bfloat162 p0 = __floats2bfloat162_rn(v0.x, v0.y);
    __nv_bfloat162 p1 = __floats2bfloat162_rn(v0.z, v0.w);
    __nv_bfloat162 p2 = __floats2bfloat162_rn(v1.x, v1.y);
    __nv_bfloat162 p3 = __floats2bfloat162_rn(v1.z, v1.w);
    uint4 o;
    o.x = *(uint32_t*)&p0; o.y = *(uint32_t*)&p1;
    o.z = *(uint32_t*)&p2; o.w = *(uint32_t*)&p3;
    *(uint4*)(y + i) = o;
}

// ---------------------------------------------------------------------------
// Tiled weight transpose: wt[n][kc] = bf16(w[kc][n]). Coalesced both ways.
// ---------------------------------------------------------------------------
__global__ void wtrans_tile(const float* __restrict__ w, __nv_bfloat16* __restrict__ wt)
{
    __shared__ float tile[32][33];
    const int kc0 = blockIdx.x * 32;
    const int n0  = blockIdx.y * 32;
    const int tx = threadIdx.x, ty = threadIdx.y;
#pragma unroll
    for (int r = ty; r < 32; r += 8)
        tile[r][tx] = w[(size_t)(kc0 + r) * HH + n0 + tx];
    __syncthreads();
#pragma unroll
    for (int r = ty; r < 32; r += 8)
        wt[(size_t)(n0 + r) * KDIM + kc0 + tx] = __float2bfloat16(tile[tx][r]);
}

// ---------------------------------------------------------------------------
__global__ __launch_bounds__(1024)
void cumsum_kernel(const int* __restrict__ dur, int* __restrict__ cum)
{
    __shared__ int buf[SS];
    const int b = blockIdx.x, tid = threadIdx.x;
    buf[tid] = dur[b * SS + tid];
    __syncthreads();
#pragma unroll
    for (int off = 1; off < SS; off <<= 1) {
        int t = buf[tid];
        int u = (tid >= off) ? buf[tid - off] : 0;
        __syncthreads();
        buf[tid] = t + u;
        __syncthreads();
    }
    cum[b * SS + tid] = buf[tid];
}

__global__ __launch_bounds__(256)
void gather_kernel(const float* __restrict__ x, const int* __restrict__ cum,
                   float* __restrict__ out)
{
    const int gw   = (blockIdx.x * 256 + threadIdx.x) >> 5;
    const int lane = threadIdx.x & 31;
    const int b = gw / MAX_OUT_T;
    const int t = gw - b * MAX_OUT_T;

    const int* c = cum + b * SS;
    const bool valid = t < c[SS - 1];
    int lo = 0, hi = SS;
    while (lo < hi) {
        int mid = (lo + hi) >> 1;
        if (c[mid] <= t) lo = mid + 1; else hi = mid;
    }
    const int src = min(lo, SS - 1);

    const float4* xin = (const float4*)(x + ((size_t)b * SS + src) * CC);
    float4* o = (float4*)(out + (size_t)gw * CC);
    const float4 z = make_float4(0.f, 0.f, 0.f, 0.f);
#pragma unroll
    for (int i = 0; i < 3; i++)
        o[lane + i * 32] = valid ? xin[lane + i * 32] : z;
}

// ---------------------------------------------------------------------------
extern "C" void kernel_launch(void* const* d_in, const int* in_sizes, int n_in,
                              void* d_out, int out_size)
{
    const float* x     = (const float*)d_in[0];
    const int*   dur   = (const int*)  d_in[1];
    const float* w1    = (const float*)d_in[2];
    const float* b1    = (const float*)d_in[3];
    const float* g1    = (const float*)d_in[4];
    const float* beta1 = (const float*)d_in[5];
    const float* w2    = (const float*)d_in[6];
    const float* b2    = (const float*)d_in[7];
    const float* g2    = (const float*)d_in[8];
    const float* beta2 = (const float*)d_in[9];
    const float* wl    = (const float*)d_in[10];
    const float* bl    = (const float*)d_in[11];
    float* out = (float*)d_out;

    __nv_bfloat16 *xb, *h1b, *wt1, *wt2, *t1b, *t2b;
    int* cum;
    cudaGetSymbolAddress((void**)&xb,   g_xb);
    cudaGetSymbolAddress((void**)&h1b,  g_h1b);
    cudaGetSymbolAddress((void**)&wt1,  g_wt1);
    cudaGetSymbolAddress((void**)&wt2,  g_wt2);
    cudaGetSymbolAddress((void**)&t1b,  g_t1b);
    cudaGetSymbolAddress((void**)&t2b,  g_t2b);
    cudaGetSymbolAddress((void**)&cum,  g_cum);

    cudaFuncSetAttribute(conv_gemm_mma, cudaFuncAttributeMaxDynamicSharedMemorySize, GEMM_SMEM);

    static cudaStream_t s2 = nullptr, s3 = nullptr;
    static cudaEvent_t  ev_fork = nullptr, ev_wt1 = nullptr, ev_wt2 = nullptr,
                        ev_join = nullptr, ev_s3 = nullptr,
                        ev_c0 = nullptr, ev_c3 = nullptr;
    if (s2 == nullptr) {
        cudaStreamCreateWithFlags(&s2, cudaStreamNonBlocking);
        cudaStreamCreateWithFlags(&s3, cudaStreamNonBlocking);
        cudaEventCreateWithFlags(&ev_fork, cudaEventDisableTiming);
        cudaEventCreateWithFlags(&ev_wt1,  cudaEventDisableTiming);
        cudaEventCreateWithFlags(&ev_wt2,  cudaEventDisableTiming);
        cudaEventCreateWithFlags(&ev_join, cudaEventDisableTiming);
        cudaEventCreateWithFlags(&ev_s3,   cudaEventDisableTiming);
        cudaEventCreateWithFlags(&ev_c0,   cudaEventDisableTiming);
        cudaEventCreateWithFlags(&ev_c3,   cudaEventDisableTiming);
    }

    // ---- fork ---------------------------------------------------------------
    cudaEventRecord(ev_fork, (cudaStream_t)0);
    cudaStreamWaitEvent(s2, ev_fork, 0);
    cudaStreamWaitEvent(s3, ev_fork, 0);

    // ---- predictor chain heads: cvt first (full DRAM, no gather contention) -
    const size_t HX = (size_t)M_HALF * CC;
    const size_t HT = (size_t)M_HALF * HH;

    f32_to_bf16<<<(M_HALF * CC) / 2048, 256>>>(x, xb);
    cudaEventRecord(ev_c0, (cudaStream_t)0);
    f32_to_bf16<<<(M_HALF * CC) / 2048, 256, 0, s3>>>(x + HX, xb + HX);
    cudaEventRecord(ev_c3, s3);

    // ---- s2: weight transposes, then (deferred) length regulation -----------
    {
        dim3 wg(KDIM / 32, HH / 32);       // (36, 12)
        wtrans_tile<<<wg, dim3(32, 8), 0, s2>>>(w1, wt1);
        cudaEventRecord(ev_wt1, s2);
        wtrans_tile<<<wg, dim3(32, 8), 0, s2>>>(w2, wt2);
        cudaEventRecord(ev_wt2, s2);
    }
    // run cumsum+gather only after both cvts (gather then overlaps the
    // DRAM-idle GEMM region instead of fighting the cvts for bandwidth)
    cudaStreamWaitEvent(s2, ev_c0, 0);
    cudaStreamWaitEvent(s2, ev_c3, 0);
    cumsum_kernel<<<BB, SS, 0, s2>>>(dur, cum);
    gather_kernel<<<(BB * MAX_OUT_T) / 8, 256, 0, s2>>>(x, cum, out);
    cudaEventRecord(ev_join, s2);

    // ---- predictor chain, two independent M-halves --------------------------
    const dim3 half_grid(HH / 128, M_HALF / 128);   // (3, 128)

    // half 0 on the main stream
    cudaStreamWaitEvent((cudaStream_t)0, ev_wt1, 0);
    conv_gemm_mma<<<half_grid, 256, GEMM_SMEM>>>(xb, wt1, b1, t1b);
    ln_relu_bf16<<<M_HALF / 8, 256>>>(t1b, g1, beta1, h1b);
    cudaStreamWaitEvent((cudaStream_t)0, ev_wt2, 0);
    conv_gemm_mma<<<half_grid, 256, GEMM_SMEM>>>(h1b, wt2, b2, t2b);
    ln_linear_exp<<<M_HALF / 8, 256>>>(t2b, g2, beta2, wl, bl, out + PRED_OFFSET);

    // half 1 on s3
    cudaStreamWaitEvent(s3, ev_wt1, 0);
    conv_gemm_mma<<<half_grid, 256, GEMM_SMEM, s3>>>(xb + HX, wt1, b1, t1b + HT);
    ln_relu_bf16<<<M_HALF / 8, 256, 0, s3>>>(t1b + HT, g1, beta1, h1b + HT);
    cudaStreamWaitEvent(s3, ev_wt2, 0);
    conv_gemm_mma<<<half_grid, 256, GEMM_SMEM, s3>>>(h1b + HT, wt2, b2, t2b + HT);
    ln_linear_exp<<<M_HALF / 8, 256, 0, s3>>>(t2b + HT, g2, beta2, wl, bl,
                                              out + PRED_OFFSET + M_HALF);
    cudaEventRecord(ev_s3, s3);

    // ---- join ----------------------------------------------------------------
    cudaStreamWaitEvent((cudaStream_t)0, ev_join, 0);
    cudaStreamWaitEvent((cudaStream_t)0, ev_s3, 0);
}

// round 17
// speedup vs baseline: 1.1183x; 1.0001x over previous
#include <cuda_runtime.h>
#include <cuda_bf16.h>
#include <math.h>
#include <stdint.h>

#define BB 32
#define SS 1024
#define CC 384
#define HH 384
#define MAX_OUT_T 3072
#define M_TOTAL (BB*SS)          // 32768
#define M_HALF  (M_TOTAL/2)      // 16384 (multiple of SS -> halo-safe split)
#define KDIM (3*CC)              // 1152
#define PRED_OFFSET ((size_t)BB*MAX_OUT_T*CC)

// ---------------- scratch (static device globals: allocation-free) ----------
__device__ __nv_bfloat16 g_xb  [(size_t)M_TOTAL*CC];
__device__ __nv_bfloat16 g_h1b [(size_t)M_TOTAL*HH];
__device__ __nv_bfloat16 g_wt1 [(size_t)HH*KDIM];
__device__ __nv_bfloat16 g_wt2 [(size_t)HH*KDIM];
__device__ __nv_bfloat16 g_t1b [(size_t)M_TOTAL*HH];
__device__ __nv_bfloat16 g_t2b [(size_t)M_TOTAL*HH];
__device__ int   g_cum[BB*SS];

// ---------------- PTX helpers (baseline PTX only) ----------------------------
__device__ __forceinline__ uint32_t smem_u32(const void* p) {
    uint32_t a;
    asm("{ .reg .u64 t; cvta.to.shared.u64 t, %1; cvt.u32.u64 %0, t; }" : "=r"(a) : "l"(p));
    return a;
}
__device__ __forceinline__ void cp_async16(uint32_t saddr, const void* gptr, uint32_t sz) {
    asm volatile("cp.async.cg.shared.global [%0], [%1], 16, %2;"
                 :: "r"(saddr), "l"(gptr), "r"(sz) : "memory");
}
__device__ __forceinline__ void cp_commit() {
    asm volatile("cp.async.commit_group;" ::: "memory");
}
template <int N>
__device__ __forceinline__ void cp_wait() {
    asm volatile("cp.async.wait_group %0;" :: "n"(N) : "memory");
}
__device__ __forceinline__ void ldmatrix_x4(uint32_t& r0, uint32_t& r1, uint32_t& r2,
                                            uint32_t& r3, uint32_t addr) {
    asm volatile("ldmatrix.sync.aligned.m8n8.x4.shared.b16 {%0,%1,%2,%3}, [%4];"
                 : "=r"(r0), "=r"(r1), "=r"(r2), "=r"(r3) : "r"(addr));
}
__device__ __forceinline__ void mma_16816(float& d0, float& d1, float& d2, float& d3,
                                          uint32_t a0, uint32_t a1, uint32_t a2, uint32_t a3,
                                          uint32_t b0, uint32_t b1) {
    asm volatile("mma.sync.aligned.m16n8k16.row.col.f32.bf16.bf16.f32 "
                 "{%0,%1,%2,%3}, {%4,%5,%6,%7}, {%8,%9}, {%0,%1,%2,%3};"
                 : "+f"(d0), "+f"(d1), "+f"(d2), "+f"(d3)
                 : "r"(a0), "r"(a1), "r"(a2), "r"(a3), "r"(b0), "r"(b1));
}

// ---------------------------------------------------------------------------
// Conv-as-GEMM, 3-tap A reuse, PAIRED steps: 9 iterations x K=128.
//   One cp_wait + one __syncthreads + one commit per iteration (was 18).
//   A: 3-slot buffer (slot j%3, 130 rows x 128B = 16640B), loaded at each
//      chunk start one chunk ahead.
//   B: 4-slot ring (slot s&3); iteration i prefetches tiles 2i+2, 2i+3
//      (slots never collide with the two being read; sync-protected).
// ---------------------------------------------------------------------------
#define NSTEPS 18
#define A_STRIDE 16640                    // 130 rows x 128 B (128B-aligned)
#define B_BASE   (3*A_STRIDE)             // 49920
#define TILE_B   16384
#define GEMM_SMEM (B_BASE + 4*TILE_B)     // 115456 -> 2 CTAs/SM (225.5KB/SM)

__global__ __launch_bounds__(256, 2)
void conv_gemm_mma(const __nv_bfloat16* __restrict__ A,
                   const __nv_bfloat16* __restrict__ Wt,
                   const float* __restrict__ bias,
                   __nv_bfloat16* __restrict__ out)
{
    extern __shared__ __align__(1024) char smem[];
    const uint32_t sbase = smem_u32(smem);
    const int tid  = threadIdx.x;
    const int wid  = tid >> 5;
    const int lane = tid & 31;
    const int warp_m = wid & 1;
    const int warp_n = wid >> 1;
    const int n0 = blockIdx.x * 128;
    const int m0 = blockIdx.y * 128;

    const int lrow = tid >> 3;              // 0..31
    const int lcx  = (tid & 7) * 16;

    auto load_A = [&](int j) {
        const uint32_t abase_w = sbase + (uint32_t)((j % 3) * A_STRIDE);
        const int c0   = j * 64;
        const int seq0 = m0 & ~(SS - 1);
#pragma unroll
        for (int i = 0; i < 5; i++) {
            const int rr = lrow + 32 * i;            // 0..159
            if (rr < 130) {
                const int xr = m0 - 1 + rr;
                const bool valid = (xr >= seq0) && (xr < seq0 + SS);
                uint32_t off = (uint32_t)(rr * 128 + lcx);
                uint32_t sw  = off ^ ((off >> 3) & 0x70);
                const char* gp = valid
                    ? ((const char*)A + ((size_t)xr * CC + c0) * 2 + lcx)
                    : (const char*)A;
                cp_async16(abase_w + sw, gp, valid ? 16u : 0u);
            }
        }
    };
    auto load_B = [&](int b) {
        const int j = b / 3, k = b - 3 * j;
        const int kc0 = k * CC + j * 64;
        const uint32_t bbase_w = sbase + B_BASE + (uint32_t)((b & 3) * TILE_B);
#pragma unroll
        for (int i = 0; i < 4; i++) {
            const int row = lrow + 32 * i;
            uint32_t off = (uint32_t)(row * 128 + lcx);
            uint32_t sw  = off ^ ((off >> 3) & 0x70);
            const char* gp = (const char*)Wt + ((size_t)(n0 + row) * KDIM + kc0) * 2 + lcx;
            cp_async16(bbase_w + sw, gp, 16u);
        }
    };

    float acc[4][4][4];
#pragma unroll
    for (int i = 0; i < 4; i++)
#pragma unroll
        for (int j = 0; j < 4; j++)
#pragma unroll
            for (int q = 0; q < 4; q++) acc[i][j][q] = 0.f;

    const int fr_row = ((lane >> 3) & 1) * 8 + (lane & 7);
    const int fr_kb  = (lane >> 4) * 16;
    const uint32_t cxor = (uint32_t)((fr_row & 7) << 4);                 // B swizzle
    const uint32_t a_row_base = (uint32_t)((warp_m * 64 + fr_row) * 128);
    const uint32_t b_row_base = (uint32_t)((warp_n * 32 + fr_row) * 128);

    // one K=64 step body (j = s/3, k = s%3)
    auto step_body = [&](int s) {
        const int j = s / 3;
        const int k = s - 3 * j;
        const uint32_t sa = sbase + (uint32_t)((j % 3) * A_STRIDE) + (uint32_t)(k * 128);
        const uint32_t sb = sbase + B_BASE + (uint32_t)((s & 3) * TILE_B);
        const uint32_t cxork = (uint32_t)(((fr_row + k) & 7) << 4);

        uint32_t ball[4][2][4];
#pragma unroll
        for (int ks = 0; ks < 4; ks++) {
            const uint32_t col = ((uint32_t)(ks * 32 + fr_kb)) ^ cxor;
#pragma unroll
            for (int nt = 0; nt < 2; nt++) {
                const uint32_t addr = sb + b_row_base + (uint32_t)(nt * 2048) + col;
                ldmatrix_x4(ball[ks][nt][0], ball[ks][nt][1], ball[ks][nt][2], ball[ks][nt][3], addr);
            }
        }
#pragma unroll
        for (int ks = 0; ks < 4; ks++) {
            const uint32_t col = ((uint32_t)(ks * 32 + fr_kb)) ^ cxork;
            uint32_t a[4][4];
#pragma unroll
            for (int mt = 0; mt < 4; mt++) {
                const uint32_t addr = sa + a_row_base + (uint32_t)(mt * 2048) + col;
                ldmatrix_x4(a[mt][0], a[mt][1], a[mt][2], a[mt][3], addr);
            }
#pragma unroll
            for (int mt = 0; mt < 4; mt++)
#pragma unroll
                for (int nt = 0; nt < 2; nt++)
#pragma unroll
                    for (int h = 0; h < 2; h++) {
                        const int jj = nt * 2 + h;
                        mma_16816(acc[mt][jj][0], acc[mt][jj][1], acc[mt][jj][2], acc[mt][jj][3],
                                  a[mt][0], a[mt][1], a[mt][2], a[mt][3],
                                  ball[ks][nt][h], ball[ks][nt][2 + h]);
                    }
        }
    };

    // prologue: group 0 = {A0, B0, B1}
    load_A(0); load_B(0); load_B(1); cp_commit();

    for (int i = 0; i < 9; ++i) {
        const int s0 = 2 * i;
        const int s1 = s0 + 1;

        cp_wait<0>();            // drain prior iteration's group
        __syncthreads();

        // prefetch next iteration's B pair + next A chunk (if pair starts one)
        if (i < 8) { load_B(s0 + 2); load_B(s1 + 2); }
        if      (s0 % 3 == 0 && s0 / 3 < 5) load_A(s0 / 3 + 1);
        else if (s1 % 3 == 0 && s1 / 3 < 5) load_A(s1 / 3 + 1);
        cp_commit();

        step_body(s0);
        step_body(s1);
    }

    // ---- epilogue: bias add, bf16 stores ------------------------------------
    const int g = lane >> 2;
    const int t = lane & 3;
#pragma unroll
    for (int mt = 0; mt < 4; mt++) {
        const int row0 = m0 + warp_m * 64 + mt * 16 + g;
#pragma unroll
        for (int j = 0; j < 4; j++) {
            const int col = n0 + warp_n * 32 + j * 8 + t * 2;
            const float2 bv = *(const float2*)(bias + col);
            __nv_bfloat162 o0 = __floats2bfloat162_rn(acc[mt][j][0] + bv.x, acc[mt][j][1] + bv.y);
            __nv_bfloat162 o1 = __floats2bfloat162_rn(acc[mt][j][2] + bv.x, acc[mt][j][3] + bv.y);
            *(__nv_bfloat162*)(out + (size_t)row0 * HH + col)       = o0;
            *(__nv_bfloat162*)(out + (size_t)(row0 + 8) * HH + col) = o1;
        }
    }
}

// ---------------------------------------------------------------------------
// Warp-per-row LayerNorm + ReLU, bf16 in -> bf16 out. fp32 math.
// ---------------------------------------------------------------------------
__global__ __launch_bounds__(256)
void ln_relu_bf16(const __nv_bfloat16* __restrict__ in, const float* __restrict__ g,
                  const float* __restrict__ beta, __nv_bfloat16* __restrict__ outb)
{
    const int row  = (blockIdx.x * 256 + threadIdx.x) >> 5;
    const int lane = threadIdx.x & 31;
    const __nv_bfloat16* p = in + (size_t)row * HH;

    float v[3][4];
    float s = 0.f, sq = 0.f;
#pragma unroll
    for (int i = 0; i < 3; i++) {
        const uint2 raw = *(const uint2*)(p + (lane + 32 * i) * 4);
        const float2 f0 = __bfloat1622float2(*(const __nv_bfloat162*)&raw.x);
        const float2 f1 = __bfloat1622float2(*(const __nv_bfloat162*)&raw.y);
        v[i][0] = f0.x; v[i][1] = f0.y; v[i][2] = f1.x; v[i][3] = f1.y;
#pragma unroll
        for (int q = 0; q < 4; q++) { s += v[i][q]; sq += v[i][q] * v[i][q]; }
    }
#pragma unroll
    for (int off = 16; off > 0; off >>= 1) {
        s  += __shfl_xor_sync(0xffffffffu, s,  off);
        sq += __shfl_xor_sync(0xffffffffu, sq, off);
    }
    const float mu = s * (1.f / HH);
    const float rs = rsqrtf(sq * (1.f / HH) - mu * mu + 1e-5f);

    __nv_bfloat16* op = outb + (size_t)row * HH;
#pragma unroll
    for (int i = 0; i < 3; i++) {
        const int c = (lane + 32 * i) * 4;
        const float4 gv = *(const float4*)(g + c);
        const float4 bv = *(const float4*)(beta + c);
        float o0 = fmaxf(0.f, (v[i][0] - mu) * rs * gv.x + bv.x);
        float o1 = fmaxf(0.f, (v[i][1] - mu) * rs * gv.y + bv.y);
        float o2 = fmaxf(0.f, (v[i][2] - mu) * rs * gv.z + bv.z);
        float o3 = fmaxf(0.f, (v[i][3] - mu) * rs * gv.w + bv.w);
        __nv_bfloat162 p0 = __floats2bfloat162_rn(o0, o1);
        __nv_bfloat162 p1 = __floats2bfloat162_rn(o2, o3);
        uint2 u; u.x = *(uint32_t*)&p0; u.y = *(uint32_t*)&p1;
        *(uint2*)(op + c) = u;
    }
}

// ---------------------------------------------------------------------------
// Warp-per-row LayerNorm + ReLU + linear(384->1) + exp, bf16 in.
// ---------------------------------------------------------------------------
__global__ __launch_bounds__(256)
void ln_linear_exp(const __nv_bfloat16* __restrict__ in, const float* __restrict__ g,
                   const float* __restrict__ beta, const float* __restrict__ wl,
                   const float* __restrict__ bl, float* __restrict__ pred)
{
    const int row  = (blockIdx.x * 256 + threadIdx.x) >> 5;
    const int lane = threadIdx.x & 31;
    const __nv_bfloat16* p = in + (size_t)row * HH;

    float v[3][4];
    float s = 0.f, sq = 0.f;
#pragma unroll
    for (int i = 0; i < 3; i++) {
        const uint2 raw = *(const uint2*)(p + (lane + 32 * i) * 4);
        const float2 f0 = __bfloat1622float2(*(const __nv_bfloat162*)&raw.x);
        const float2 f1 = __bfloat1622float2(*(const __nv_bfloat162*)&raw.y);
        v[i][0] = f0.x; v[i][1] = f0.y; v[i][2] = f1.x; v[i][3] = f1.y;
#pragma unroll
        for (int q = 0; q < 4; q++) { s += v[i][q]; sq += v[i][q] * v[i][q]; }
    }
#pragma unroll
    for (int off = 16; off > 0; off >>= 1) {
        s  += __shfl_xor_sync(0xffffffffu, s,  off);
        sq += __shfl_xor_sync(0xffffffffu, sq, off);
    }
    const float mu = s * (1.f / HH);
    const float rs = rsqrtf(sq * (1.f / HH) - mu * mu + 1e-5f);

    float d = 0.f;
#pragma unroll
    for (int i = 0; i < 3; i++) {
        const int c = (lane + 32 * i) * 4;
        const float4 gv = *(const float4*)(g + c);
        const float4 bv = *(const float4*)(beta + c);
        const float4 wv = *(const float4*)(wl + c);
        d += fmaxf(0.f, (v[i][0] - mu) * rs * gv.x + bv.x) * wv.x;
        d += fmaxf(0.f, (v[i][1] - mu) * rs * gv.y + bv.y) * wv.y;
        d += fmaxf(0.f, (v[i][2] - mu) * rs * gv.z + bv.z) * wv.z;
        d += fmaxf(0.f, (v[i][3] - mu) * rs * gv.w + bv.w) * wv.w;
    }
#pragma unroll
    for (int off = 16; off > 0; off >>= 1)
        d += __shfl_xor_sync(0xffffffffu, d, off);
    if (lane == 0) pred[row] = expf(d + bl[0]);
}

// ---------------------------------------------------------------------------
// fp32 -> bf16 convert, 8 elements/thread (two independent float4 loads).
// ---------------------------------------------------------------------------
__global__ __launch_bounds__(256)
void f32_to_bf16(const float* __restrict__ x, __nv_bfloat16* __restrict__ y)
{
    const size_t i = ((size_t)blockIdx.x * 256 + threadIdx.x) * 8;
    const float4 v0 = *(const float4*)(x + i);
    const float4 v1 = *(const float4*)(x + i + 4);
    __nv_bfloat162 p0 = __floats2bfloat162_rn(v0.x, v0.y);
    __nv_bfloat162 p1 = __floats2bfloat162_rn(v0.z, v0.w);
    __nv_bfloat162 p2 = __floats2bfloat162_rn(v1.x, v1.y);
    __nv_bfloat162 p3 = __floats2bfloat162_rn(v1.z, v1.w);
    uint4 o;
    o.x = *(uint32_t*)&p0; o.y = *(uint32_t*)&p1;
    o.z = *(uint32_t*)&p2; o.w = *(uint32_t*)&p3;
    *(uint4*)(y + i) = o;
}

// ---------------------------------------------------------------------------
// Tiled weight transpose: wt[n][kc] = bf16(w[kc][n]). Coalesced both ways.
// ---------------------------------------------------------------------------
__global__ void wtrans_tile(const float* __restrict__ w, __nv_bfloat16* __restrict__ wt)
{
    __shared__ float tile[32][33];
    const int kc0 = blockIdx.x * 32;
    const int n0  = blockIdx.y * 32;
    const int tx = threadIdx.x, ty = threadIdx.y;
#pragma unroll
    for (int r = ty; r < 32; r += 8)
        tile[r][tx] = w[(size_t)(kc0 + r) * HH + n0 + tx];
    __syncthreads();
#pragma unroll
    for (int r = ty; r < 32; r += 8)
        wt[(size_t)(n0 + r) * KDIM + kc0 + tx] = __float2bfloat16(tile[tx][r]);
}

// ---------------------------------------------------------------------------
__global__ __launch_bounds__(1024)
void cumsum_kernel(const int* __restrict__ dur, int* __restrict__ cum)
{
    __shared__ int buf[SS];
    const int b = blockIdx.x, tid = threadIdx.x;
    buf[tid] = dur[b * SS + tid];
    __syncthreads();
#pragma unroll
    for (int off = 1; off < SS; off <<= 1) {
        int t = buf[tid];
        int u = (tid >= off) ? buf[tid - off] : 0;
        __syncthreads();
        buf[tid] = t + u;
        __syncthreads();
    }
    cum[b * SS + tid] = buf[tid];
}

__global__ __launch_bounds__(256)
void gather_kernel(const float* __restrict__ x, const int* __restrict__ cum,
                   float* __restrict__ out)
{
    const int gw   = (blockIdx.x * 256 + threadIdx.x) >> 5;
    const int lane = threadIdx.x & 31;
    const int b = gw / MAX_OUT_T;
    const int t = gw - b * MAX_OUT_T;

    const int* c = cum + b * SS;
    const bool valid = t < c[SS - 1];
    int lo = 0, hi = SS;
    while (lo < hi) {
        int mid = (lo + hi) >> 1;
        if (c[mid] <= t) lo = mid + 1; else hi = mid;
    }
    const int src = min(lo, SS - 1);

    const float4* xin = (const float4*)(x + ((size_t)b * SS + src) * CC);
    float4* o = (float4*)(out + (size_t)gw * CC);
    const float4 z = make_float4(0.f, 0.f, 0.f, 0.f);
#pragma unroll
    for (int i = 0; i < 3; i++)
        o[lane + i * 32] = valid ? xin[lane + i * 32] : z;
}

// ---------------------------------------------------------------------------
extern "C" void kernel_launch(void* const* d_in, const int* in_sizes, int n_in,
                              void* d_out, int out_size)
{
    const float* x     = (const float*)d_in[0];
    const int*   dur   = (const int*)  d_in[1];
    const float* w1    = (const float*)d_in[2];
    const float* b1    = (const float*)d_in[3];
    const float* g1    = (const float*)d_in[4];
    const float* beta1 = (const float*)d_in[5];
    const float* w2    = (const float*)d_in[6];
    const float* b2    = (const float*)d_in[7];
    const float* g2    = (const float*)d_in[8];
    const float* beta2 = (const float*)d_in[9];
    const float* wl    = (const float*)d_in[10];
    const float* bl    = (const float*)d_in[11];
    float* out = (float*)d_out;

    __nv_bfloat16 *xb, *h1b, *wt1, *wt2, *t1b, *t2b;
    int* cum;
    cudaGetSymbolAddress((void**)&xb,   g_xb);
    cudaGetSymbolAddress((void**)&h1b,  g_h1b);
    cudaGetSymbolAddress((void**)&wt1,  g_wt1);
    cudaGetSymbolAddress((void**)&wt2,  g_wt2);
    cudaGetSymbolAddress((void**)&t1b,  g_t1b);
    cudaGetSymbolAddress((void**)&t2b,  g_t2b);
    cudaGetSymbolAddress((void**)&cum,  g_cum);

    cudaFuncSetAttribute(conv_gemm_mma, cudaFuncAttributeMaxDynamicSharedMemorySize, GEMM_SMEM);

    static cudaStream_t s2 = nullptr, s3 = nullptr;
    static cudaEvent_t  ev_fork = nullptr, ev_wt1 = nullptr, ev_wt2 = nullptr,
                        ev_join = nullptr, ev_s3 = nullptr,
                        ev_c0 = nullptr, ev_c3 = nullptr;
    if (s2 == nullptr) {
        cudaStreamCreateWithFlags(&s2, cudaStreamNonBlocking);
        cudaStreamCreateWithFlags(&s3, cudaStreamNonBlocking);
        cudaEventCreateWithFlags(&ev_fork, cudaEventDisableTiming);
        cudaEventCreateWithFlags(&ev_wt1,  cudaEventDisableTiming);
        cudaEventCreateWithFlags(&ev_wt2,  cudaEventDisableTiming);
        cudaEventCreateWithFlags(&ev_join, cudaEventDisableTiming);
        cudaEventCreateWithFlags(&ev_s3,   cudaEventDisableTiming);
        cudaEventCreateWithFlags(&ev_c0,   cudaEventDisableTiming);
        cudaEventCreateWithFlags(&ev_c3,   cudaEventDisableTiming);
    }

    // ---- fork ---------------------------------------------------------------
    cudaEventRecord(ev_fork, (cudaStream_t)0);
    cudaStreamWaitEvent(s2, ev_fork, 0);
    cudaStreamWaitEvent(s3, ev_fork, 0);

    // ---- predictor chain heads: cvt first (full DRAM, no gather contention) -
    const size_t HX = (size_t)M_HALF * CC;
    const size_t HT = (size_t)M_HALF * HH;

    f32_to_bf16<<<(M_HALF * CC) / 2048, 256>>>(x, xb);
    cudaEventRecord(ev_c0, (cudaStream_t)0);
    f32_to_bf16<<<(M_HALF * CC) / 2048, 256, 0, s3>>>(x + HX, xb + HX);
    cudaEventRecord(ev_c3, s3);

    // ---- s2: weight transposes, then (deferred) length regulation -----------
    {
        dim3 wg(KDIM / 32, HH / 32);       // (36, 12)
        wtrans_tile<<<wg, dim3(32, 8), 0, s2>>>(w1, wt1);
        cudaEventRecord(ev_wt1, s2);
        wtrans_tile<<<wg, dim3(32, 8), 0, s2>>>(w2, wt2);
        cudaEventRecord(ev_wt2, s2);
    }
    cudaStreamWaitEvent(s2, ev_c0, 0);
    cudaStreamWaitEvent(s2, ev_c3, 0);
    cumsum_kernel<<<BB, SS, 0, s2>>>(dur, cum);
    gather_kernel<<<(BB * MAX_OUT_T) / 8, 256, 0, s2>>>(x, cum, out);
    cudaEventRecord(ev_join, s2);

    // ---- predictor chain, two independent M-halves --------------------------
    const dim3 half_grid(HH / 128, M_HALF / 128);   // (3, 128)

    // half 0 on the main stream
    cudaStreamWaitEvent((cudaStream_t)0, ev_wt1, 0);
    conv_gemm_mma<<<half_grid, 256, GEMM_SMEM>>>(xb, wt1, b1, t1b);
    ln_relu_bf16<<<M_HALF / 8, 256>>>(t1b, g1, beta1, h1b);
    cudaStreamWaitEvent((cudaStream_t)0, ev_wt2, 0);
    conv_gemm_mma<<<half_grid, 256, GEMM_SMEM>>>(h1b, wt2, b2, t2b);
    ln_linear_exp<<<M_HALF / 8, 256>>>(t2b, g2, beta2, wl, bl, out + PRED_OFFSET);

    // half 1 on s3
    cudaStreamWaitEvent(s3, ev_wt1, 0);
    conv_gemm_mma<<<half_grid, 256, GEMM_SMEM, s3>>>(xb + HX, wt1, b1, t1b + HT);
    ln_relu_bf16<<<M_HALF / 8, 256, 0, s3>>>(t1b + HT, g1, beta1, h1b + HT);
    cudaStreamWaitEvent(s3, ev_wt2, 0);
    conv_gemm_mma<<<half_grid, 256, GEMM_SMEM, s3>>>(h1b + HT, wt2, b2, t2b + HT);
    ln_linear_exp<<<M_HALF / 8, 256, 0, s3>>>(t2b + HT, g2, beta2, wl, bl,
                                              out + PRED_OFFSET + M_HALF);
    cudaEventRecord(ev_s3, s3);

    // ---- join ----------------------------------------------------------------
    cudaStreamWaitEvent((cudaStream_t)0, ev_join, 0);
    cudaStreamWaitEvent((cudaStream_t)0, ev_s3, 0);
}